// round 3
// baseline (speedup 1.0000x reference)
#include <cuda_runtime.h>
#include <cstdint>
#include <cstddef>

// ---------------- problem constants ----------------
constexpr int B_   = 2;
constexpr int L_   = 2048;
constexpr int DIM_ = 512;
constexpr int DIN_ = 1024;
constexpr int DST_ = 16;
constexpr int BL_  = B_ * L_;          // 4096 rows
#define LOG2E_F 1.4426950408889634f

// ---------------- scratch (static device globals; no allocation) ----------------
__device__ float g_xn    [(size_t)BL_ * DIM_];        // LN1 output
__device__ float g_ul    [(size_t)BL_ * 2 * DIN_];    // in_proj output [u | z]
__device__ float g_ucf   [(size_t)BL_ * DIN_];        // conv+silu fwd
__device__ float g_ucb   [(size_t)BL_ * DIN_];        // conv+silu bwd (reversed time)
__device__ float g_xdblf [(size_t)BL_ * 64];          // x_proj fwd [dt|B|C]
__device__ float g_xdblb [(size_t)BL_ * 64];
__device__ float g_deltaf[(size_t)BL_ * DIN_];
__device__ float g_deltab[(size_t)BL_ * DIN_];
__device__ float g_ysf   [(size_t)BL_ * DIN_];        // scan output fwd
__device__ float g_ysb   [(size_t)BL_ * DIN_];        // scan output bwd (reversed time)
__device__ float g_yc    [(size_t)BL_ * DIN_];        // combined y
__device__ float g_outpre[(size_t)BL_ * DIM_];        // out_proj output

__device__ __forceinline__ float* get_buf(int id) {
    switch (id) {
        case 0: return g_xn;
        case 1: return g_ul;
        case 2: return g_ucf;
        case 3: return g_ucb;
        case 4: return g_xdblf;
        case 5: return g_xdblb;
        case 6: return g_deltaf;
        case 7: return g_deltab;
        case 8: return g_yc;
        default: return g_outpre;
    }
}

// ---------------- small math helpers ----------------
__device__ __forceinline__ float ex2f_(float x) {
    float y; asm("ex2.approx.ftz.f32 %0, %1;" : "=f"(y) : "f"(x)); return y;
}
__device__ __forceinline__ float silu_f(float x) {
    return x / (1.0f + ex2f_(-LOG2E_F * x));
}
__device__ __forceinline__ float softplus_f(float x) {
    return fmaxf(x, 0.0f) + log1pf(__expf(-fabsf(x)));
}
__device__ __forceinline__ unsigned f2tf(float x) {
    unsigned r; asm("cvt.rna.tf32.f32 %0, %1;" : "=r"(r) : "f"(x)); return r;
}
__device__ __forceinline__ void mma_tf32(float c[4], const unsigned a[4],
                                         unsigned b0, unsigned b1) {
    asm volatile(
        "mma.sync.aligned.m16n8k8.row.col.f32.tf32.tf32.f32 "
        "{%0,%1,%2,%3}, {%4,%5,%6,%7}, {%8,%9}, {%0,%1,%2,%3};"
        : "+f"(c[0]), "+f"(c[1]), "+f"(c[2]), "+f"(c[3])
        : "r"(a[0]), "r"(a[1]), "r"(a[2]), "r"(a[3]), "r"(b0), "r"(b1));
}

// ---------------- LayerNorm (mode 0: LN1 x->g_xn; mode 1: LN2 (g_outpre+x)->out) ----
__global__ __launch_bounds__(128) void ln_kernel(
    const float* __restrict__ x, const float* __restrict__ w,
    const float* __restrict__ bvec, float* __restrict__ outp, int mode)
{
    __shared__ float red[8];
    const int row = blockIdx.x;
    const int tid = threadIdx.x;     // 128 threads, 4 floats each (DIM=512)

    float4 v = reinterpret_cast<const float4*>(x + (size_t)row * DIM_)[tid];
    if (mode) {
        float4 r = reinterpret_cast<const float4*>(g_outpre + (size_t)row * DIM_)[tid];
        v.x += r.x; v.y += r.y; v.z += r.z; v.w += r.w;
    }
    float s  = v.x + v.y + v.z + v.w;
    float ss = v.x*v.x + v.y*v.y + v.z*v.z + v.w*v.w;
    #pragma unroll
    for (int o = 16; o; o >>= 1) {
        s  += __shfl_xor_sync(0xffffffffu, s,  o);
        ss += __shfl_xor_sync(0xffffffffu, ss, o);
    }
    if ((tid & 31) == 0) { red[tid >> 5] = s; red[4 + (tid >> 5)] = ss; }
    __syncthreads();
    s  = red[0] + red[1] + red[2] + red[3];
    ss = red[4] + red[5] + red[6] + red[7];
    const float mean = s * (1.0f / DIM_);
    const float var  = ss * (1.0f / DIM_) - mean * mean;
    const float inv  = rsqrtf(var + 1e-5f);

    float4 wv = reinterpret_cast<const float4*>(w)[tid];
    float4 bv = reinterpret_cast<const float4*>(bvec)[tid];
    float4 o4;
    o4.x = (v.x - mean) * inv * wv.x + bv.x;
    o4.y = (v.y - mean) * inv * wv.y + bv.y;
    o4.z = (v.z - mean) * inv * wv.z + bv.z;
    o4.w = (v.w - mean) * inv * wv.w + bv.w;
    float* dst = mode ? outp : g_xn;
    reinterpret_cast<float4*>(dst + (size_t)row * DIM_)[tid] = o4;
}

// ---------------- tf32 tensor-core GEMM: C(M,N) = A(M,K) @ W(N,K)^T ----------------
// Block tile 128x64, BK=16, 256 threads, 8 warps (4 m x 2 n), warp tile 32x32.
// EPI: 0 = none, 1 = +bias[n] then softplus (writes delta directly).
template <int EPI>
__global__ __launch_bounds__(256) void gemm_tf32_kernel(
    int M, int N, int Kd,
    int aid, int lda,
    const float* __restrict__ W, int ldw,
    int cid, int ldc,
    const float* __restrict__ bias)
{
    __shared__ __align__(16) unsigned sA[128 * 20];   // [row][k], stride 20 (pad)
    __shared__ __align__(16) unsigned sW[64 * 20];    // [n]  [k], stride 20

    const float* __restrict__ A = get_buf(aid);
    float* __restrict__ C = get_buf(cid);

    const int tid  = threadIdx.x;
    const int lane = tid & 31;
    const int warp = tid >> 5;
    const int g    = lane >> 2;       // 0..7
    const int tig  = lane & 3;        // 0..3
    const int wm   = warp & 3;        // 0..3 (m)
    const int wn   = warp >> 2;       // 0..1 (n)
    const int m0   = blockIdx.y * 128;
    const int n0   = blockIdx.x * 64;

    float acc[2][4][4];
    #pragma unroll
    for (int i = 0; i < 2; i++)
        #pragma unroll
        for (int j = 0; j < 4; j++)
            #pragma unroll
            for (int q = 0; q < 4; q++) acc[i][j][q] = 0.0f;

    const int ar = tid >> 1, ak = (tid & 1) * 8;       // A staging: 2 float4/thread
    const int wr = tid >> 2, wk = (tid & 3) * 4;       // W staging: 1 float4/thread
    const float* Ap = A + (size_t)(m0 + ar) * lda + ak;
    const float* Wp = W + (size_t)(n0 + wr) * ldw + wk;

    for (int k0 = 0; k0 < Kd; k0 += 16) {
        float4 a0 = *reinterpret_cast<const float4*>(Ap + k0);
        float4 a1 = *reinterpret_cast<const float4*>(Ap + k0 + 4);
        float4 w0 = *reinterpret_cast<const float4*>(Wp + k0);
        unsigned* pa = &sA[ar * 20 + ak];
        *reinterpret_cast<uint4*>(pa)     = make_uint4(f2tf(a0.x), f2tf(a0.y), f2tf(a0.z), f2tf(a0.w));
        *reinterpret_cast<uint4*>(pa + 4) = make_uint4(f2tf(a1.x), f2tf(a1.y), f2tf(a1.z), f2tf(a1.w));
        *reinterpret_cast<uint4*>(&sW[wr * 20 + wk]) =
            make_uint4(f2tf(w0.x), f2tf(w0.y), f2tf(w0.z), f2tf(w0.w));
        __syncthreads();

        #pragma unroll
        for (int ks = 0; ks < 16; ks += 8) {
            unsigned af[2][4];
            #pragma unroll
            for (int im = 0; im < 2; im++) {
                const int base = (wm * 32 + im * 16 + g) * 20 + ks;
                af[im][0] = sA[base + tig];
                af[im][1] = sA[base + 160 + tig];       // +8 rows
                af[im][2] = sA[base + 4 + tig];
                af[im][3] = sA[base + 160 + 4 + tig];
            }
            #pragma unroll
            for (int in = 0; in < 4; in++) {
                const int nb = (wn * 32 + in * 8 + g) * 20 + ks;
                const unsigned b0 = sW[nb + tig];
                const unsigned b1 = sW[nb + 4 + tig];
                #pragma unroll
                for (int im = 0; im < 2; im++)
                    mma_tf32(acc[im][in], af[im], b0, b1);
            }
        }
        __syncthreads();
    }

    // epilogue
    #pragma unroll
    for (int im = 0; im < 2; im++) {
        #pragma unroll
        for (int in = 0; in < 4; in++) {
            const int row = m0 + wm * 32 + im * 16 + g;
            const int col = n0 + wn * 32 + in * 8 + 2 * tig;
            float v0 = acc[im][in][0], v1 = acc[im][in][1];
            float v2 = acc[im][in][2], v3 = acc[im][in][3];
            if (EPI == 1) {
                const float bc0 = bias[col], bc1 = bias[col + 1];
                v0 = softplus_f(v0 + bc0); v1 = softplus_f(v1 + bc1);
                v2 = softplus_f(v2 + bc0); v3 = softplus_f(v3 + bc1);
            }
            *reinterpret_cast<float2*>(&C[(size_t)row * ldc + col])       = make_float2(v0, v1);
            *reinterpret_cast<float2*>(&C[(size_t)(row + 8) * ldc + col]) = make_float2(v2, v3);
        }
    }
}

// ---------------- depthwise causal conv (K=4) + SiLU, both branches ----------------
// br==0: uc_f[t] = silu(bias + sum_k w[k]*u[t-3+k])           (zero for t-3+k<0)
// br==1: uc_b[t'] on the reversed sequence: u_rev[s] = u[L-1-s]
__global__ __launch_bounds__(256) void conv_silu_kernel(
    const float* __restrict__ wf, const float* __restrict__ biasf,
    const float* __restrict__ wb, const float* __restrict__ biasb)
{
    const int br = blockIdx.y;
    const int i  = blockIdx.x * 256 + threadIdx.x;     // over BL*DIN
    const int d  = i & (DIN_ - 1);
    const int t  = (i >> 10) & (L_ - 1);
    const int b  = i >> 21;

    const float* w = br ? wb : wf;
    float acc = (br ? biasb : biasf)[d];
    #pragma unroll
    for (int k = 0; k < 4; k++) {
        const int s = t - 3 + k;
        if (s >= 0) {
            const int tt = br ? (L_ - 1 - s) : s;
            acc += w[d * 4 + k] * g_ul[((size_t)(b * L_ + tt) << 11) + d];  // u = ul[:, :DIN]
        }
    }
    const float r = silu_f(acc);
    float* out = br ? g_ucb : g_ucf;
    out[((size_t)(b * L_ + t) << 10) + d] = r;
}

// ---------------- selective scan ----------------
// thread = (state n, local channel dl); block = 32 channels x 16 states = 512 thr
// grid = (DIN/32, B, 2 branches). h-recurrence: h = exp(delta*A)*h + delta*u*B; y = <h,C>
__global__ __launch_bounds__(512) void scan_kernel(
    const float* __restrict__ AlogF, const float* __restrict__ AlogB)
{
    const int br = blockIdx.z;
    const int b  = blockIdx.y;
    const int d0 = blockIdx.x * 32;
    const int tid = threadIdx.x;
    const int n  = tid & 15;
    const int dl = tid >> 4;
    const int d  = d0 + dl;

    const float* __restrict__ delta = br ? g_deltab : g_deltaf;
    const float* __restrict__ xdbl  = br ? g_xdblb  : g_xdblf;
    const float* __restrict__ uc    = br ? g_ucb    : g_ucf;
    const float* __restrict__ Alog  = br ? AlogB    : AlogF;
    float* __restrict__ ys          = br ? g_ysb    : g_ysf;

    // A = -exp(A_log); pre-fold log2(e) so the step uses EX2 directly
    const float AL2 = -__expf(Alog[d * DST_ + n]) * LOG2E_F;

    __shared__ float sdelta[64][33];
    __shared__ float sdu[64][33];
    __shared__ float sbc[64][32];   // [ B(0..15) | C(16..31) ]
    __shared__ float sy[64][33];

    float h = 0.0f;

    for (int t0 = 0; t0 < L_; t0 += 64) {
        // stage 64 timesteps (coalesced; delta*u precomputed once per channel)
        #pragma unroll
        for (int i = tid; i < 64 * 32; i += 512) {
            const int tt = i >> 5, c = i & 31;
            const size_t gi = ((size_t)(b * L_ + t0 + tt) << 10) + d0 + c;
            const float dv = delta[gi];
            sdelta[tt][c] = dv;
            sdu[tt][c]    = dv * uc[gi];
            sbc[tt][c]    = xdbl[((size_t)(b * L_ + t0 + tt) << 6) + 32 + c];
        }
        __syncthreads();

        #pragma unroll 8
        for (int tt = 0; tt < 64; tt++) {
            const float dv  = sdelta[tt][dl];
            const float du  = sdu[tt][dl];
            const float bb  = sbc[tt][n];
            const float cc  = sbc[tt][16 + n];
            const float e   = ex2f_(dv * AL2);
            h = fmaf(e, h, du * bb);
            float p = h * cc;
            p += __shfl_xor_sync(0xffffffffu, p, 1);
            p += __shfl_xor_sync(0xffffffffu, p, 2);
            p += __shfl_xor_sync(0xffffffffu, p, 4);
            p += __shfl_xor_sync(0xffffffffu, p, 8);
            if (n == 0) sy[tt][dl] = p;
        }
        __syncthreads();

        #pragma unroll
        for (int i = tid; i < 64 * 32; i += 512) {
            const int tt = i >> 5, c = i & 31;
            ys[((size_t)(b * L_ + t0 + tt) << 10) + d0 + c] = sy[tt][c];
        }
        // staging of next tile is ordered vs sy reads by the sync after staging
    }
}

// ---------------- combine: yc = g*(ys_f + uc_f*D_f) + g*rev(ys_b + uc_b*D_b) -------
__global__ __launch_bounds__(256) void combine_kernel(
    const float* __restrict__ Df, const float* __restrict__ Db)
{
    const int i = blockIdx.x * 256 + threadIdx.x;      // over BL*DIN
    const int d = i & (DIN_ - 1);
    const int t = (i >> 10) & (L_ - 1);
    const int b = i >> 21;

    const float z  = g_ul[((size_t)(b * L_ + t) << 11) + DIN_ + d];
    const float gg = silu_f(z);
    const size_t fi = (size_t)i;
    const size_t bi = ((size_t)(b * L_ + (L_ - 1 - t)) << 10) + d;
    const float yf = g_ysf[fi] + g_ucf[fi] * Df[d];
    const float yr = g_ysb[bi] + g_ucb[bi] * Db[d];
    g_yc[fi] = gg * (yf + yr);
}

// ---------------- launch ----------------
extern "C" void kernel_launch(void* const* d_in, const int* in_sizes, int n_in,
                              void* d_out, int out_size)
{
    const float* x          = (const float*)d_in[0];
    const float* ln1_w      = (const float*)d_in[1];
    const float* ln1_b      = (const float*)d_in[2];
    const float* ln2_w      = (const float*)d_in[3];
    const float* ln2_b      = (const float*)d_in[4];
    const float* in_proj_w  = (const float*)d_in[5];
    const float* conv_w_fw  = (const float*)d_in[6];
    const float* conv_b_fw  = (const float*)d_in[7];
    const float* xproj_w_fw = (const float*)d_in[8];
    const float* dt_w_fw    = (const float*)d_in[9];
    const float* dt_b_fw    = (const float*)d_in[10];
    const float* A_log_fw   = (const float*)d_in[11];
    const float* D_fw       = (const float*)d_in[12];
    const float* conv_w_bw  = (const float*)d_in[13];
    const float* conv_b_bw  = (const float*)d_in[14];
    const float* xproj_w_bw = (const float*)d_in[15];
    const float* dt_w_bw    = (const float*)d_in[16];
    const float* dt_b_bw    = (const float*)d_in[17];
    const float* A_log_bw   = (const float*)d_in[18];
    const float* D_bw       = (const float*)d_in[19];
    const float* out_proj_w = (const float*)d_in[20];
    float* out = (float*)d_out;

    // 1) LN1: x -> g_xn
    ln_kernel<<<BL_, 128>>>(x, ln1_w, ln1_b, nullptr, 0);

    // 2) in_proj: g_xn(4096,512) @ in_proj_w(2048,512)^T -> g_ul(4096,2048)
    gemm_tf32_kernel<0><<<dim3(2048 / 64, BL_ / 128), 256>>>(
        BL_, 2048, 512, /*A*/0, 512, in_proj_w, 512, /*C*/1, 2048, nullptr);

    // 3) causal conv + SiLU, fwd + bwd(reversed)
    conv_silu_kernel<<<dim3((BL_ * DIN_) / 256, 2), 256>>>(
        conv_w_fw, conv_b_fw, conv_w_bw, conv_b_bw);

    // 4) x_proj: uc(4096,1024) @ xproj_w(64,1024)^T -> xdbl(4096,64)
    gemm_tf32_kernel<0><<<dim3(1, BL_ / 128), 256>>>(
        BL_, 64, 1024, /*A*/2, 1024, xproj_w_fw, 1024, /*C*/4, 64, nullptr);
    gemm_tf32_kernel<0><<<dim3(1, BL_ / 128), 256>>>(
        BL_, 64, 1024, /*A*/3, 1024, xproj_w_bw, 1024, /*C*/5, 64, nullptr);

    // 5) delta = softplus(dt(4096,32) @ dt_w(1024,32)^T + dt_b)
    gemm_tf32_kernel<1><<<dim3(1024 / 64, BL_ / 128), 256>>>(
        BL_, 1024, 32, /*A*/4, 64, dt_w_fw, 32, /*C*/6, 1024, dt_b_fw);
    gemm_tf32_kernel<1><<<dim3(1024 / 64, BL_ / 128), 256>>>(
        BL_, 1024, 32, /*A*/5, 64, dt_w_bw, 32, /*C*/7, 1024, dt_b_bw);

    // 6) selective scans (both branches concurrent via grid.z)
    scan_kernel<<<dim3(DIN_ / 32, B_, 2), 512>>>(A_log_fw, A_log_bw);

    // 7) combine with gate g = silu(z)
    combine_kernel<<<(BL_ * DIN_) / 256, 256>>>(D_fw, D_bw);

    // 8) out_proj: g_yc(4096,1024) @ out_proj_w(512,1024)^T -> g_outpre(4096,512)
    gemm_tf32_kernel<0><<<dim3(512 / 64, BL_ / 128), 256>>>(
        BL_, 512, 1024, /*A*/8, 1024, out_proj_w, 1024, /*C*/9, 512, nullptr);

    // 9) LN2(residual + out_pre) -> d_out
    ln_kernel<<<BL_, 128>>>(x, ln2_w, ln2_b, out, 1);
}